// round 1
// baseline (speedup 1.0000x reference)
#include <cuda_runtime.h>
#include <cuda_bf16.h>
#include <cstddef>

// ---------------------------------------------------------------------------
// Problem constants
// ---------------------------------------------------------------------------
#define BATCH   8
#define SEQ     1024
#define DIM     768
#define HEADS   12
#define DHEAD   64
#define INNER   768           // HEADS * DHEAD
#define MLPDIM  3072
#define ROWS    (BATCH * SEQ) // 8192
#define QKVC    (3 * INNER)   // 2304

// ---------------------------------------------------------------------------
// Scratch (device globals: allocation is forbidden)
// ---------------------------------------------------------------------------
__device__ float g_h   [ (size_t)ROWS * DIM   ];  // LN1 output
__device__ float g_qkv [ (size_t)ROWS * QKVC  ];  // fused QKV
__device__ float g_attn[ (size_t)ROWS * INNER ];  // attention output
__device__ float g_x1  [ (size_t)ROWS * DIM   ];  // post-attention residual
__device__ float g_h2  [ (size_t)ROWS * DIM   ];  // LN2 output
__device__ float g_mlp [ (size_t)ROWS * MLPDIM];  // GELU(h @ w1 + b1)

// ---------------------------------------------------------------------------
// LayerNorm: one block per row, two-pass (mean, then var) for fp32 accuracy
// ---------------------------------------------------------------------------
__global__ __launch_bounds__(256) void ln_kernel(
    const float* __restrict__ x, const float* __restrict__ g,
    const float* __restrict__ b, float* __restrict__ y)
{
    const int row = blockIdx.x;
    const float* xr = x + (size_t)row * DIM;
    __shared__ float sh[DIM];
    __shared__ float red[256];
    const int t = threadIdx.x;

    float s = 0.f;
    for (int c = t; c < DIM; c += 256) { float v = xr[c]; sh[c] = v; s += v; }
    red[t] = s; __syncthreads();
    #pragma unroll
    for (int off = 128; off > 0; off >>= 1) {
        if (t < off) red[t] += red[t + off];
        __syncthreads();
    }
    const float mu = red[0] * (1.f / DIM);
    __syncthreads();

    float s2 = 0.f;
    for (int c = t; c < DIM; c += 256) { float d = sh[c] - mu; s2 += d * d; }
    red[t] = s2; __syncthreads();
    #pragma unroll
    for (int off = 128; off > 0; off >>= 1) {
        if (t < off) red[t] += red[t + off];
        __syncthreads();
    }
    const float var = red[0] * (1.f / DIM);
    const float inv = rsqrtf(var + 1e-5f);

    float* yr = y + (size_t)row * DIM;
    for (int c = t; c < DIM; c += 256)
        yr[c] = (sh[c] - mu) * inv * g[c] + b[c];
}

// ---------------------------------------------------------------------------
// SGEMM: C[M,N] = A[M,K] @ B[K,N] (+ epilogue). 128x128 tile, BK=8, 8x8/thread
// ---------------------------------------------------------------------------
#define EPI_NONE      0
#define EPI_RES       1   // + Res
#define EPI_BIAS_GELU 2   // gelu(. + bias)     (tanh approximation, jax default)
#define EPI_BIAS_RES  3   // + bias + Res

__device__ __forceinline__ float gelu_tanh(float x) {
    return 0.5f * x * (1.0f + tanhf(0.7978845608028654f * (x + 0.044715f * x * x * x)));
}

template <int EPI>
__global__ __launch_bounds__(256) void sgemm_kernel(
    const float* __restrict__ A, const float* __restrict__ B,
    const float* __restrict__ bias, const float* __restrict__ Res,
    float* __restrict__ C, int M, int N, int K)
{
    const int br = blockIdx.y, bc = blockIdx.x;
    __shared__ float As[8][128];
    __shared__ float Bs[8][128];
    const int tid = threadIdx.x;

    A += (size_t)br * 128 * K;
    B += (size_t)bc * 128;

    float acc[8][8];
    #pragma unroll
    for (int i = 0; i < 8; i++)
        #pragma unroll
        for (int j = 0; j < 8; j++) acc[i][j] = 0.f;

    const int arow = tid >> 1, acol = (tid & 1) << 2;   // 128 rows x 8 cols (A tile)
    const int brow = tid >> 5, bcol = (tid & 31) << 2;  // 8 rows x 128 cols (B tile)
    const int tr = (tid >> 4) << 3, tc = (tid & 15) << 3;

    for (int k0 = 0; k0 < K; k0 += 8) {
        float4 av = *(const float4*)(A + (size_t)arow * K + k0 + acol);
        As[acol + 0][arow] = av.x;
        As[acol + 1][arow] = av.y;
        As[acol + 2][arow] = av.z;
        As[acol + 3][arow] = av.w;
        float4 bv = *(const float4*)(B + (size_t)(k0 + brow) * N + bcol);
        *(float4*)&Bs[brow][bcol] = bv;
        __syncthreads();

        #pragma unroll
        for (int k = 0; k < 8; k++) {
            float ra[8], rb[8];
            #pragma unroll
            for (int i = 0; i < 8; i++) ra[i] = As[k][tr + i];
            #pragma unroll
            for (int j = 0; j < 8; j++) rb[j] = Bs[k][tc + j];
            #pragma unroll
            for (int i = 0; i < 8; i++)
                #pragma unroll
                for (int j = 0; j < 8; j++) acc[i][j] += ra[i] * rb[j];
        }
        __syncthreads();
    }

    const int gr0 = br * 128 + tr;
    const int gc0 = bc * 128 + tc;
    #pragma unroll
    for (int i = 0; i < 8; i++) {
        const size_t base = (size_t)(gr0 + i) * N + gc0;
        float v[8];
        #pragma unroll
        for (int j = 0; j < 8; j++) {
            float c = acc[i][j];
            if (EPI == EPI_BIAS_GELU) {
                c += bias[gc0 + j];
                c = gelu_tanh(c);
            } else if (EPI == EPI_BIAS_RES) {
                c += bias[gc0 + j] + Res[base + j];
            } else if (EPI == EPI_RES) {
                c += Res[base + j];
            }
            v[j] = c;
        }
        *(float4*)(C + base)     = make_float4(v[0], v[1], v[2], v[3]);
        *(float4*)(C + base + 4) = make_float4(v[4], v[5], v[6], v[7]);
    }
}

// ---------------------------------------------------------------------------
// Fused flash-style attention.
// Grid: (SEQ/64, HEADS, BATCH), 256 threads.
// Each block: 64 query rows of one (b,h); streams key/value tiles of 64 with
// online softmax. Thread t -> query row i = t/4, output cols c0 = (t%4)*16.
// Dynamic smem: Qs,Ks,Vs,Ss = 4 * 64*65 floats + m,l.
// ---------------------------------------------------------------------------
#define ATTN_SMEM_FLOATS (4 * 64 * 65 + 128)
#define ATTN_SMEM_BYTES  (ATTN_SMEM_FLOATS * 4)

__global__ __launch_bounds__(256) void attn_kernel(
    const float* __restrict__ qkv, float* __restrict__ out)
{
    extern __shared__ float sm[];
    float* Qs  = sm;                 // [64][65]
    float* Ks  = Qs + 64 * 65;
    float* Vs  = Ks + 64 * 65;
    float* Ss  = Vs + 64 * 65;
    float* m_s = Ss + 64 * 65;       // [64]
    float* l_s = m_s + 64;           // [64]

    const int b  = blockIdx.z;
    const int h  = blockIdx.y;
    const int n0 = blockIdx.x * 64;
    const int t  = threadIdx.x;
    const float scale = 0.125f;      // DHEAD^-0.5

    const float* qbase = qkv + ((size_t)b * SEQ + n0) * QKVC + h * DHEAD;
    const float* kbase = qkv + ((size_t)b * SEQ) * QKVC + INNER + h * DHEAD;
    const float* vbase = kbase + INNER;

    // Load & pre-scale the Q tile
    for (int idx = t; idx < 64 * 16; idx += 256) {
        const int r = idx >> 4, c4 = (idx & 15) << 2;
        float4 v = *(const float4*)(qbase + (size_t)r * QKVC + c4);
        Qs[r * 65 + c4 + 0] = v.x * scale;
        Qs[r * 65 + c4 + 1] = v.y * scale;
        Qs[r * 65 + c4 + 2] = v.z * scale;
        Qs[r * 65 + c4 + 3] = v.w * scale;
    }
    if (t < 64) { m_s[t] = -1e30f; l_s[t] = 0.f; }

    const int i  = t >> 2;           // query row within the tile
    const int qd = t & 3;            // quad lane
    const int c0 = qd * 16;          // column / key-chunk base

    float o[16];
    #pragma unroll
    for (int c = 0; c < 16; c++) o[c] = 0.f;

    for (int kt = 0; kt < SEQ / 64; kt++) {
        const int kn0 = kt * 64;
        for (int idx = t; idx < 64 * 16; idx += 256) {
            const int r = idx >> 4, c4 = (idx & 15) << 2;
            float4 kv = *(const float4*)(kbase + (size_t)(kn0 + r) * QKVC + c4);
            Ks[r * 65 + c4 + 0] = kv.x; Ks[r * 65 + c4 + 1] = kv.y;
            Ks[r * 65 + c4 + 2] = kv.z; Ks[r * 65 + c4 + 3] = kv.w;
            float4 vv = *(const float4*)(vbase + (size_t)(kn0 + r) * QKVC + c4);
            Vs[r * 65 + c4 + 0] = vv.x; Vs[r * 65 + c4 + 1] = vv.y;
            Vs[r * 65 + c4 + 2] = vv.z; Vs[r * 65 + c4 + 3] = vv.w;
        }
        __syncthreads();

        // S = (Q*scale) . K^T for this thread's 16 keys
        float s[16];
        #pragma unroll
        for (int jj = 0; jj < 16; jj++) s[jj] = 0.f;
        #pragma unroll 4
        for (int d = 0; d < 64; d++) {
            const float q = Qs[i * 65 + d];
            #pragma unroll
            for (int jj = 0; jj < 16; jj++)
                s[jj] += q * Ks[(c0 + jj) * 65 + d];
        }

        // Row max across the 4-lane group
        float tmax = s[0];
        #pragma unroll
        for (int jj = 1; jj < 16; jj++) tmax = fmaxf(tmax, s[jj]);
        tmax = fmaxf(tmax, __shfl_xor_sync(0xffffffffu, tmax, 1));
        tmax = fmaxf(tmax, __shfl_xor_sync(0xffffffffu, tmax, 2));

        const float mold = m_s[i];
        const float mnew = fmaxf(mold, tmax);

        float psum = 0.f;
        #pragma unroll
        for (int jj = 0; jj < 16; jj++) {
            const float p = __expf(s[jj] - mnew);
            Ss[i * 65 + c0 + jj] = p;
            psum += p;
        }
        psum += __shfl_xor_sync(0xffffffffu, psum, 1);
        psum += __shfl_xor_sync(0xffffffffu, psum, 2);

        const float factor = __expf(mold - mnew);
        #pragma unroll
        for (int c = 0; c < 16; c++) o[c] *= factor;
        if (qd == 0) {
            m_s[i] = mnew;
            l_s[i] = l_s[i] * factor + psum;
        }
        __syncthreads();

        // O += P . V  (this thread: row i, cols c0..c0+15)
        #pragma unroll 4
        for (int j = 0; j < 64; j++) {
            const float p = Ss[i * 65 + j];
            #pragma unroll
            for (int c = 0; c < 16; c++)
                o[c] += p * Vs[j * 65 + c0 + c];
        }
        __syncthreads();
    }

    const float invl = 1.f / l_s[i];
    float* obase = out + ((size_t)b * SEQ + n0 + i) * INNER + h * DHEAD + c0;
    #pragma unroll
    for (int c = 0; c < 16; c++) obase[c] = o[c] * invl;
}

// ---------------------------------------------------------------------------
// Launch
// ---------------------------------------------------------------------------
extern "C" void kernel_launch(void* const* d_in, const int* in_sizes, int n_in,
                              void* d_out, int out_size)
{
    const float* x     = (const float*)d_in[0];
    const float* ln1_g = (const float*)d_in[1];
    const float* ln1_b = (const float*)d_in[2];
    const float* w_qkv = (const float*)d_in[3];
    const float* w_out = (const float*)d_in[4];
    const float* ln2_g = (const float*)d_in[5];
    const float* ln2_b = (const float*)d_in[6];
    const float* w1    = (const float*)d_in[7];
    const float* b1    = (const float*)d_in[8];
    const float* w2    = (const float*)d_in[9];
    const float* b2    = (const float*)d_in[10];
    float* out = (float*)d_out;

    float *h, *qkv, *attn, *x1, *h2, *mlp;
    cudaGetSymbolAddress((void**)&h,    g_h);
    cudaGetSymbolAddress((void**)&qkv,  g_qkv);
    cudaGetSymbolAddress((void**)&attn, g_attn);
    cudaGetSymbolAddress((void**)&x1,   g_x1);
    cudaGetSymbolAddress((void**)&h2,   g_h2);
    cudaGetSymbolAddress((void**)&mlp,  g_mlp);

    cudaFuncSetAttribute(attn_kernel,
                         cudaFuncAttributeMaxDynamicSharedMemorySize,
                         ATTN_SMEM_BYTES);

    // 1) LN1
    ln_kernel<<<ROWS, 256>>>(x, ln1_g, ln1_b, h);
    // 2) QKV = h @ w_qkv            [8192 x 2304 x 768]
    sgemm_kernel<EPI_NONE><<<dim3(QKVC / 128, ROWS / 128), 256>>>(
        h, w_qkv, nullptr, nullptr, qkv, ROWS, QKVC, DIM);
    // 3) attention
    attn_kernel<<<dim3(SEQ / 64, HEADS, BATCH), 256, ATTN_SMEM_BYTES>>>(qkv, attn);
    // 4) x1 = attn @ w_out + x      [8192 x 768 x 768]
    sgemm_kernel<EPI_RES><<<dim3(DIM / 128, ROWS / 128), 256>>>(
        attn, w_out, nullptr, x, x1, ROWS, DIM, INNER);
    // 5) LN2
    ln_kernel<<<ROWS, 256>>>(x1, ln2_g, ln2_b, h2);
    // 6) mlp = gelu(h2 @ w1 + b1)   [8192 x 3072 x 768]
    sgemm_kernel<EPI_BIAS_GELU><<<dim3(MLPDIM / 128, ROWS / 128), 256>>>(
        h2, w1, b1, nullptr, mlp, ROWS, MLPDIM, DIM);
    // 7) out = mlp @ w2 + b2 + x1   [8192 x 768 x 3072]
    sgemm_kernel<EPI_BIAS_RES><<<dim3(DIM / 128, ROWS / 128), 256>>>(
        mlp, w2, b2, x1, out, ROWS, DIM, MLPDIM);
}

// round 3
// speedup vs baseline: 1.5332x; 1.5332x over previous
#include <cuda_runtime.h>
#include <cuda_bf16.h>
#include <cstdint>
#include <cstddef>

// ---------------------------------------------------------------------------
// Problem constants
// ---------------------------------------------------------------------------
#define BATCH   8
#define SEQ     1024
#define DIM     768
#define HEADS   12
#define DHEAD   64
#define INNER   768
#define MLPDIM  3072
#define ROWS    (BATCH * SEQ) // 8192
#define QKVC    (3 * INNER)   // 2304

typedef __nv_bfloat16 bf16;

// ---------------------------------------------------------------------------
// Scratch (device globals: allocation is forbidden)
// ---------------------------------------------------------------------------
__device__ float g_h   [ (size_t)ROWS * DIM   ];
__device__ float g_qkv [ (size_t)ROWS * QKVC  ];
__device__ float g_attn[ (size_t)ROWS * INNER ];
__device__ float g_x1  [ (size_t)ROWS * DIM   ];
__device__ float g_h2  [ (size_t)ROWS * DIM   ];
__device__ float g_mlp [ (size_t)ROWS * MLPDIM];

__device__ bf16 g_act_hi[(size_t)ROWS * MLPDIM];
__device__ bf16 g_act_lo[(size_t)ROWS * MLPDIM];
__device__ bf16 g_wqkvT_hi[(size_t)QKVC  * DIM];
__device__ bf16 g_wqkvT_lo[(size_t)QKVC  * DIM];
__device__ bf16 g_woutT_hi[(size_t)DIM   * INNER];
__device__ bf16 g_woutT_lo[(size_t)DIM   * INNER];
__device__ bf16 g_w1T_hi [(size_t)MLPDIM * DIM];
__device__ bf16 g_w1T_lo [(size_t)MLPDIM * DIM];
__device__ bf16 g_w2T_hi [(size_t)DIM    * MLPDIM];
__device__ bf16 g_w2T_lo [(size_t)DIM    * MLPDIM];

// ---------------------------------------------------------------------------
// PTX helpers (baseline sm_80+ ISA only — ptxas target here is sm_100 plain)
// ---------------------------------------------------------------------------
__device__ __forceinline__ uint32_t smem_u32(const void* p) {
    uint32_t a;
    asm("{ .reg .u64 t; cvta.to.shared.u64 t, %1; cvt.u32.u64 %0, t; }"
        : "=r"(a) : "l"(p));
    return a;
}
__device__ __forceinline__ void cp16(uint32_t dst, const void* src) {
    asm volatile("cp.async.cg.shared.global [%0], [%1], 16;\n"
                 :: "r"(dst), "l"(src) : "memory");
}
__device__ __forceinline__ void ldsm4(uint32_t* r, uint32_t addr) {
    asm volatile("ldmatrix.sync.aligned.m8n8.x4.shared.b16 {%0,%1,%2,%3}, [%4];"
                 : "=r"(r[0]), "=r"(r[1]), "=r"(r[2]), "=r"(r[3]) : "r"(addr));
}
__device__ __forceinline__ void mma_bf16(float* c, const uint32_t* a,
                                         const uint32_t* b) {
    asm volatile(
        "mma.sync.aligned.m16n8k16.row.col.f32.bf16.bf16.f32 "
        "{%0,%1,%2,%3}, {%4,%5,%6,%7}, {%8,%9}, {%0,%1,%2,%3};"
        : "+f"(c[0]), "+f"(c[1]), "+f"(c[2]), "+f"(c[3])
        : "r"(a[0]), "r"(a[1]), "r"(a[2]), "r"(a[3]), "r"(b[0]), "r"(b[1]));
}

// ---------------------------------------------------------------------------
// LayerNorm
// ---------------------------------------------------------------------------
__global__ __launch_bounds__(256) void ln_kernel(
    const float* __restrict__ x, const float* __restrict__ g,
    const float* __restrict__ b, float* __restrict__ y)
{
    const int row = blockIdx.x;
    const float* xr = x + (size_t)row * DIM;
    __shared__ float sh[DIM];
    __shared__ float red[256];
    const int t = threadIdx.x;

    float s = 0.f;
    for (int c = t; c < DIM; c += 256) { float v = xr[c]; sh[c] = v; s += v; }
    red[t] = s; __syncthreads();
    #pragma unroll
    for (int off = 128; off > 0; off >>= 1) {
        if (t < off) red[t] += red[t + off];
        __syncthreads();
    }
    const float mu = red[0] * (1.f / DIM);
    __syncthreads();

    float s2 = 0.f;
    for (int c = t; c < DIM; c += 256) { float d = sh[c] - mu; s2 += d * d; }
    red[t] = s2; __syncthreads();
    #pragma unroll
    for (int off = 128; off > 0; off >>= 1) {
        if (t < off) red[t] += red[t + off];
        __syncthreads();
    }
    const float var = red[0] * (1.f / DIM);
    const float inv = rsqrtf(var + 1e-5f);

    float* yr = y + (size_t)row * DIM;
    for (int c = t; c < DIM; c += 256)
        yr[c] = (sh[c] - mu) * inv * g[c] + b[c];
}

// ---------------------------------------------------------------------------
// fp32 -> bf16 hi/lo split (elementwise, float4 vectorized)
// ---------------------------------------------------------------------------
__global__ __launch_bounds__(256) void split_kernel(
    const float* __restrict__ x, bf16* __restrict__ hi,
    bf16* __restrict__ lo, int n4)
{
    int i = blockIdx.x * 256 + threadIdx.x;
    if (i >= n4) return;
    float4 v = ((const float4*)x)[i];
    bf16 h0 = __float2bfloat16(v.x);
    bf16 h1 = __float2bfloat16(v.y);
    bf16 h2 = __float2bfloat16(v.z);
    bf16 h3 = __float2bfloat16(v.w);
    __nv_bfloat162 ph0; ph0.x = h0; ph0.y = h1;
    __nv_bfloat162 ph1; ph1.x = h2; ph1.y = h3;
    __nv_bfloat162 pl0;
    pl0.x = __float2bfloat16(v.x - __bfloat162float(h0));
    pl0.y = __float2bfloat16(v.y - __bfloat162float(h1));
    __nv_bfloat162 pl1;
    pl1.x = __float2bfloat16(v.z - __bfloat162float(h2));
    pl1.y = __float2bfloat16(v.w - __bfloat162float(h3));
    ((__nv_bfloat162*)hi)[i * 2]     = ph0;
    ((__nv_bfloat162*)hi)[i * 2 + 1] = ph1;
    ((__nv_bfloat162*)lo)[i * 2]     = pl0;
    ((__nv_bfloat162*)lo)[i * 2 + 1] = pl1;
}

// ---------------------------------------------------------------------------
// W[K,N] -> Wt[N,K] transpose + bf16 hi/lo split (32x32 tiles)
// ---------------------------------------------------------------------------
__global__ __launch_bounds__(256) void transpose_split_kernel(
    const float* __restrict__ W, bf16* __restrict__ Thi,
    bf16* __restrict__ Tlo, int K, int N)
{
    __shared__ float tl[32][33];
    const int n0 = blockIdx.x * 32, k0 = blockIdx.y * 32;
    const int tx = threadIdx.x & 31, ty = threadIdx.x >> 5; // 32 x 8

    #pragma unroll
    for (int r = 0; r < 4; r++)
        tl[ty + 8 * r][tx] = W[(size_t)(k0 + ty + 8 * r) * N + n0 + tx];
    __syncthreads();
    #pragma unroll
    for (int r = 0; r < 4; r++) {
        const int n = n0 + ty + 8 * r;
        const int k = k0 + tx;
        float v = tl[tx][ty + 8 * r];
        bf16 h = __float2bfloat16(v);
        Thi[(size_t)n * K + k] = h;
        Tlo[(size_t)n * K + k] = __float2bfloat16(v - __bfloat162float(h));
    }
}

// ---------------------------------------------------------------------------
// bf16x3 tensor-core GEMM via mma.sync: C[M,N] = A[M,K] @ Wt[N,K]^T (+epi)
// 128x128 CTA tile, BK=64, 8 warps (2x4), warp tile 64x32, m16n8k16.
// smem: 2 stages x 4 tiles (Ahi,Alo,Bhi,Blo) x 16KB, SW128 swizzle.
// ---------------------------------------------------------------------------
#define EPI_NONE      0
#define EPI_RES       1
#define EPI_BIAS_GELU 2
#define EPI_BIAS_RES  3

__device__ __forceinline__ float gelu_tanh(float x) {
    return 0.5f * x * (1.0f + tanhf(0.7978845608028654f * (x + 0.044715f * x * x * x)));
}

#define GEMM_SMEM (2 * 65536)

template <int EPI>
__global__ __launch_bounds__(256, 1) void gemm_mma(
    const bf16* __restrict__ Ahi, const bf16* __restrict__ Alo,
    const bf16* __restrict__ Bhi, const bf16* __restrict__ Blo,
    const float* __restrict__ bias, const float* __restrict__ Res,
    float* __restrict__ C, int M, int N, int K)
{
    extern __shared__ char smem[];
    const uint32_t sbase = smem_u32(smem);
    const int tid = threadIdx.x, wid = tid >> 5, lid = tid & 31;
    const int rowA0 = blockIdx.y * 128, colB0 = blockIdx.x * 128;
    const int m0 = (wid >> 2) * 64, n0 = (wid & 3) * 32;

    const bf16* gbase[4] = {
        Ahi + (size_t)rowA0 * K, Alo + (size_t)rowA0 * K,
        Bhi + (size_t)colB0 * K, Blo + (size_t)colB0 * K };

    const int NK = K >> 6;

    float acc[4][4][4];
    #pragma unroll
    for (int i = 0; i < 4; i++)
        #pragma unroll
        for (int j = 0; j < 4; j++)
            #pragma unroll
            for (int r = 0; r < 4; r++) acc[i][j][r] = 0.f;

    // ---- chunk loader: 4 tiles x 128 rows x 128B, SW128 swizzled ----
    auto load_chunk = [&](int kc, int s) {
        const uint32_t stg = sbase + s * 65536;
        #pragma unroll
        for (int p = 0; p < 16; p++) {
            const int id   = tid + (p << 8);
            const int tile = id >> 10;
            const int wi   = id & 1023;
            const int row  = wi >> 3, ch = wi & 7;
            const bf16* src = gbase[tile] + (size_t)row * K + (kc << 6) + (ch << 3);
            const uint32_t off = (row << 7) + (ch << 4);
            cp16(stg + (tile << 14) + (off ^ ((off >> 3) & 0x70)), src);
        }
        asm volatile("cp.async.commit_group;\n" ::: "memory");
    };

    // per-thread ldmatrix address roles
    const int rA  = lid & 15;          // A: row within 16-row tile
    const int cbA = lid >> 4;          // A: k-chunk select (0/1)
    const int rB  = ((lid >> 4) << 3) + (lid & 7); // B: row within 16-n-row pair
    const int cbB = (lid >> 3) & 1;    // B: k-chunk select

    load_chunk(0, 0);

    for (int kc = 0; kc < NK; kc++) {
        const int s = kc & 1;
        if (kc + 1 < NK) {
            load_chunk(kc + 1, (kc + 1) & 1);
            asm volatile("cp.async.wait_group 1;\n" ::: "memory");
        } else {
            asm volatile("cp.async.wait_group 0;\n" ::: "memory");
        }
        __syncthreads();

        const uint32_t stg = sbase + s * 65536;
        #pragma unroll
        for (int ks = 0; ks < 4; ks++) {
            uint32_t ah[4][4], al[4][4], bh[4][2], bl[4][2];
            #pragma unroll
            for (int i = 0; i < 4; i++) {
                const int row = m0 + i * 16 + rA;
                const uint32_t off =
                    (row << 7) + (((ks * 2 + cbA) ^ (rA & 7)) << 4);
                ldsm4(ah[i], stg + off);            // Ahi at +0
                ldsm4(al[i], stg + 16384 + off);    // Alo
            }
            #pragma unroll
            for (int j2 = 0; j2 < 2; j2++) {
                const int row = n0 + j2 * 16 + rB;
                const uint32_t off =
                    (row << 7) + (((ks * 2 + cbB) ^ (rB & 7)) << 4);
                uint32_t t4[4];
                ldsm4(t4, stg + 32768 + off);       // Bhi
                bh[j2 * 2][0] = t4[0]; bh[j2 * 2][1] = t4[1];
                bh[j2 * 2 + 1][0] = t4[2]; bh[j2 * 2 + 1][1] = t4[3];
                ldsm4(t4, stg + 49152 + off);       // Blo
                bl[j2 * 2][0] = t4[0]; bl[j2 * 2][1] = t4[1];
                bl[j2 * 2 + 1][0] = t4[2]; bl[j2 * 2 + 1][1] = t4[3];
            }
            #pragma unroll
            for (int i = 0; i < 4; i++)
                #pragma unroll
                for (int j = 0; j < 4; j++) {
                    mma_bf16(acc[i][j], ah[i], bh[j]); // hi*hi
                    mma_bf16(acc[i][j], al[i], bh[j]); // lo*hi
                    mma_bf16(acc[i][j], ah[i], bl[j]); // hi*lo
                }
        }
        __syncthreads();
    }

    // ---- epilogue: direct gmem stores (float2 per fragment row) ----
    const int g = lid >> 2, q = lid & 3;
    #pragma unroll
    for (int i = 0; i < 4; i++)
        #pragma unroll
        for (int j = 0; j < 4; j++) {
            const int row0 = rowA0 + m0 + i * 16 + g;
            const int col  = colB0 + n0 + j * 8 + 2 * q;
            #pragma unroll
            for (int half = 0; half < 2; half++) {
                const int row = row0 + half * 8;
                const size_t idx = (size_t)row * N + col;
                float c0 = acc[i][j][half * 2 + 0];
                float c1 = acc[i][j][half * 2 + 1];
                if (EPI == EPI_BIAS_GELU) {
                    c0 = gelu_tanh(c0 + bias[col]);
                    c1 = gelu_tanh(c1 + bias[col + 1]);
                } else if (EPI == EPI_BIAS_RES) {
                    c0 += bias[col]     + Res[idx];
                    c1 += bias[col + 1] + Res[idx + 1];
                } else if (EPI == EPI_RES) {
                    c0 += Res[idx];
                    c1 += Res[idx + 1];
                }
                *(float2*)(C + idx) = make_float2(c0, c1);
            }
        }
}

// ---------------------------------------------------------------------------
// Fused flash-style attention (unchanged — next round's target)
// ---------------------------------------------------------------------------
#define ATTN_SMEM_FLOATS (4 * 64 * 65 + 128)
#define ATTN_SMEM_BYTES  (ATTN_SMEM_FLOATS * 4)

__global__ __launch_bounds__(256) void attn_kernel(
    const float* __restrict__ qkv, float* __restrict__ out)
{
    extern __shared__ float sm[];
    float* Qs  = sm;
    float* Ks  = Qs + 64 * 65;
    float* Vs  = Ks + 64 * 65;
    float* Ss  = Vs + 64 * 65;
    float* m_s = Ss + 64 * 65;
    float* l_s = m_s + 64;

    const int b  = blockIdx.z;
    const int h  = blockIdx.y;
    const int n0 = blockIdx.x * 64;
    const int t  = threadIdx.x;
    const float scale = 0.125f;

    const float* qbase = qkv + ((size_t)b * SEQ + n0) * QKVC + h * DHEAD;
    const float* kbase = qkv + ((size_t)b * SEQ) * QKVC + INNER + h * DHEAD;
    const float* vbase = kbase + INNER;

    for (int idx = t; idx < 64 * 16; idx += 256) {
        const int r = idx >> 4, c4 = (idx & 15) << 2;
        float4 v = *(const float4*)(qbase + (size_t)r * QKVC + c4);
        Qs[r * 65 + c4 + 0] = v.x * scale;
        Qs[r * 65 + c4 + 1] = v.y * scale;
        Qs[r * 65 + c4 + 2] = v.z * scale;
        Qs[r * 65 + c4 + 3] = v.w * scale;
    }
    if (t < 64) { m_s[t] = -1e30f; l_s[t] = 0.f; }

    const int i  = t >> 2;
    const int qd = t & 3;
    const int c0 = qd * 16;

    float o[16];
    #pragma unroll
    for (int c = 0; c < 16; c++) o[c] = 0.f;

    for (int kt = 0; kt < SEQ / 64; kt++) {
        const int kn0 = kt * 64;
        for (int idx = t; idx < 64 * 16; idx += 256) {
            const int r = idx >> 4, c4 = (idx & 15) << 2;
            float4 kv = *(const float4*)(kbase + (size_t)(kn0 + r) * QKVC + c4);
            Ks[r * 65 + c4 + 0] = kv.x; Ks[r * 65 + c4 + 1] = kv.y;
            Ks[r * 65 + c4 + 2] = kv.z; Ks[r * 65 + c4 + 3] = kv.w;
            float4 vv = *(const float4*)(vbase + (size_t)(kn0 + r) * QKVC + c4);
            Vs[r * 65 + c4 + 0] = vv.x; Vs[r * 65 + c4 + 1] = vv.y;
            Vs[r * 65 + c4 + 2] = vv.z; Vs[r * 65 + c4 + 3] = vv.w;
        }
        __syncthreads();

        float s[16];
        #pragma unroll
        for (int jj = 0; jj < 16; jj++) s[jj] = 0.f;
        #pragma unroll 4
        for (int d = 0; d < 64; d++) {
            const float q = Qs[i * 65 + d];
            #pragma unroll
            for (int jj = 0; jj < 16; jj++)
                s[jj] += q * Ks[(c0 + jj) * 65 + d];
        }

        float tmax = s[0];
        #pragma unroll
        for (int jj = 1; jj < 16; jj++) tmax = fmaxf(tmax, s[jj]);
        tmax = fmaxf(tmax, __shfl_xor_sync(0xffffffffu, tmax, 1));
        tmax = fmaxf(tmax, __shfl_xor_sync(0xffffffffu, tmax, 2));

        const float mold = m_s[i];
        const float mnew = fmaxf(mold, tmax);

        float psum = 0.f;
        #pragma unroll
        for (int jj = 0; jj < 16; jj++) {
            const float p = __expf(s[jj] - mnew);
            Ss[i * 65 + c0 + jj] = p;
            psum += p;
        }
        psum += __shfl_xor_sync(0xffffffffu, psum, 1);
        psum += __shfl_xor_sync(0xffffffffu, psum, 2);

        const float factor = __expf(mold - mnew);
        #pragma unroll
        for (int c = 0; c < 16; c++) o[c] *= factor;
        if (qd == 0) {
            m_s[i] = mnew;
            l_s[i] = l_s[i] * factor + psum;
        }
        __syncthreads();

        #pragma unroll 4
        for (int j = 0; j < 64; j++) {
            const float p = Ss[i * 65 + j];
            #pragma unroll
            for (int c = 0; c < 16; c++)
                o[c] += p * Vs[j * 65 + c0 + c];
        }
        __syncthreads();
    }

    const float invl = 1.f / l_s[i];
    float* obase = out + ((size_t)b * SEQ + n0 + i) * INNER + h * DHEAD + c0;
    #pragma unroll
    for (int c = 0; c < 16; c++) obase[c] = o[c] * invl;
}

// ---------------------------------------------------------------------------
// Launch
// ---------------------------------------------------------------------------
extern "C" void kernel_launch(void* const* d_in, const int* in_sizes, int n_in,
                              void* d_out, int out_size)
{
    const float* x     = (const float*)d_in[0];
    const float* ln1_g = (const float*)d_in[1];
    const float* ln1_b = (const float*)d_in[2];
    const float* w_qkv = (const float*)d_in[3];
    const float* w_out = (const float*)d_in[4];
    const float* ln2_g = (const float*)d_in[5];
    const float* ln2_b = (const float*)d_in[6];
    const float* w1    = (const float*)d_in[7];
    const float* b1    = (const float*)d_in[8];
    const float* w2    = (const float*)d_in[9];
    const float* b2    = (const float*)d_in[10];
    float* out = (float*)d_out;

    float *h, *qkv, *attn, *x1, *h2, *mlp;
    cudaGetSymbolAddress((void**)&h,    g_h);
    cudaGetSymbolAddress((void**)&qkv,  g_qkv);
    cudaGetSymbolAddress((void**)&attn, g_attn);
    cudaGetSymbolAddress((void**)&x1,   g_x1);
    cudaGetSymbolAddress((void**)&h2,   g_h2);
    cudaGetSymbolAddress((void**)&mlp,  g_mlp);

    bf16 *ahi, *alo;
    bf16 *qkvT_hi, *qkvT_lo, *outT_hi, *outT_lo;
    bf16 *w1T_hi, *w1T_lo, *w2T_hi, *w2T_lo;
    cudaGetSymbolAddress((void**)&ahi,     g_act_hi);
    cudaGetSymbolAddress((void**)&alo,     g_act_lo);
    cudaGetSymbolAddress((void**)&qkvT_hi, g_wqkvT_hi);
    cudaGetSymbolAddress((void**)&qkvT_lo, g_wqkvT_lo);
    cudaGetSymbolAddress((void**)&outT_hi, g_woutT_hi);
    cudaGetSymbolAddress((void**)&outT_lo, g_woutT_lo);
    cudaGetSymbolAddress((void**)&w1T_hi,  g_w1T_hi);
    cudaGetSymbolAddress((void**)&w1T_lo,  g_w1T_lo);
    cudaGetSymbolAddress((void**)&w2T_hi,  g_w2T_hi);
    cudaGetSymbolAddress((void**)&w2T_lo,  g_w2T_lo);

    cudaFuncSetAttribute(attn_kernel,
        cudaFuncAttributeMaxDynamicSharedMemorySize, ATTN_SMEM_BYTES);
    cudaFuncSetAttribute(gemm_mma<EPI_NONE>,
        cudaFuncAttributeMaxDynamicSharedMemorySize, GEMM_SMEM);
    cudaFuncSetAttribute(gemm_mma<EPI_RES>,
        cudaFuncAttributeMaxDynamicSharedMemorySize, GEMM_SMEM);
    cudaFuncSetAttribute(gemm_mma<EPI_BIAS_GELU>,
        cudaFuncAttributeMaxDynamicSharedMemorySize, GEMM_SMEM);
    cudaFuncSetAttribute(gemm_mma<EPI_BIAS_RES>,
        cudaFuncAttributeMaxDynamicSharedMemorySize, GEMM_SMEM);

    // Weight transpose + split
    transpose_split_kernel<<<dim3(QKVC / 32, DIM / 32), 256>>>(
        w_qkv, qkvT_hi, qkvT_lo, DIM, QKVC);
    transpose_split_kernel<<<dim3(DIM / 32, INNER / 32), 256>>>(
        w_out, outT_hi, outT_lo, INNER, DIM);
    transpose_split_kernel<<<dim3(MLPDIM / 32, DIM / 32), 256>>>(
        w1, w1T_hi, w1T_lo, DIM, MLPDIM);
    transpose_split_kernel<<<dim3(DIM / 32, MLPDIM / 32), 256>>>(
        w2, w2T_hi, w2T_lo, MLPDIM, DIM);

    // 1) LN1
    ln_kernel<<<ROWS, 256>>>(x, ln1_g, ln1_b, h);
    // 2) QKV = h @ w_qkv
    split_kernel<<<(ROWS * DIM / 4 + 255) / 256, 256>>>(h, ahi, alo, ROWS * DIM / 4);
    gemm_mma<EPI_NONE><<<dim3(QKVC / 128, ROWS / 128), 256, GEMM_SMEM>>>(
        ahi, alo, qkvT_hi, qkvT_lo, nullptr, nullptr, qkv, ROWS, QKVC, DIM);
    // 3) attention
    attn_kernel<<<dim3(SEQ / 64, HEADS, BATCH), 256, ATTN_SMEM_BYTES>>>(qkv, attn);
    // 4) x1 = attn @ w_out + x
    split_kernel<<<(ROWS * INNER / 4 + 255) / 256, 256>>>(attn, ahi, alo, ROWS * INNER / 4);
    gemm_mma<EPI_RES><<<dim3(DIM / 128, ROWS / 128), 256, GEMM_SMEM>>>(
        ahi, alo, outT_hi, outT_lo, nullptr, x, x1, ROWS, DIM, INNER);
    // 5) LN2
    ln_kernel<<<ROWS, 256>>>(x1, ln2_g, ln2_b, h2);
    // 6) mlp = gelu(h2 @ w1 + b1)
    split_kernel<<<(ROWS * DIM / 4 + 255) / 256, 256>>>(h2, ahi, alo, ROWS * DIM / 4);
    gemm_mma<EPI_BIAS_GELU><<<dim3(MLPDIM / 128, ROWS / 128), 256, GEMM_SMEM>>>(
        ahi, alo, w1T_hi, w1T_lo, b1, nullptr, mlp, ROWS, MLPDIM, DIM);
    // 7) out = mlp @ w2 + b2 + x1
    split_kernel<<<(ROWS * MLPDIM / 4 + 255) / 256, 256>>>(mlp, ahi, alo, ROWS * MLPDIM / 4);
    gemm_mma<EPI_BIAS_RES><<<dim3(DIM / 128, ROWS / 128), 256, GEMM_SMEM>>>(
        ahi, alo, w2T_hi, w2T_lo, b2, x1, out, ROWS, DIM, MLPDIM);
}